// round 11
// baseline (speedup 1.0000x reference)
#include <cuda_runtime.h>
#include <cuda_bf16.h>
#include <cstdint>
#include <math.h>

// ---------------- problem constants ----------------
#define BATCH 32
#define NFRM  16
#define HW    192        // H*W = 8*24
#define DIM   256
#define NSLOT 21
#define NACT  20
#define ROWS_KV (BATCH*NFRM*HW)   // 98304
#define ROWS_S  (BATCH*NSLOT)     // 672
#define SLOTS_OUT_SIZE (BATCH*NACT*DIM)  // 163840
#define ATTN_EPS 1e-8f
#define LN_EPS   1e-5f
#define SCALE    0.0625f   // 256^-0.5
#define TPB 512            // slot_iter threads per CTA

// ---------------- scratch (static device globals; no allocs) ----------------
__device__ float g_xn  [ROWS_KV*DIM];
__device__ float g_k   [ROWS_KV*DIM];
__device__ float g_v   [ROWS_KV*DIM];
__device__ float g_slots[ROWS_S*DIM];
__device__ float g_q   [ROWS_S*DIM];
__device__ float g_attn[BATCH*NSLOT*HW];
__device__ float g_upd [ROWS_S*DIM];
__device__ float g_gi  [ROWS_S*3*DIM];
__device__ float g_gh  [ROWS_S*3*DIM];
__device__ float g_h   [ROWS_S*DIM];
__device__ float g_f1  [ROWS_S*DIM];
// k-major transposed weights [k=256][n]
__device__ float g_wqt [DIM*DIM];
__device__ float g_w1t [DIM*DIM];
__device__ float g_w2t [DIM*DIM];
__device__ float g_wiht[DIM*3*DIM];
__device__ float g_whht[DIM*3*DIM];

// ---------------- smem layout (floats) for persistent kernel ----------------
// GEMMs read A rows up to 23 (rows >= 21 are discarded garbage); every A
// buffer is followed by enough other smem that overshoot reads stay inside
// the dynamic allocation.
#define LDA     260            // row stride for 21x256 activation buffers
#define SZ_ACT  (NSLOT*LDA)    // 5460
#define OFF_SLOTS 0
#define OFF_SLN   (OFF_SLOTS + SZ_ACT)
#define OFF_Q     (OFF_SLN   + SZ_ACT)
#define OFF_UPD   (OFF_Q     + SZ_ACT)
#define OFF_H     (OFF_UPD   + SZ_ACT)
#define OFF_HLN   (OFF_H     + SZ_ACT)
#define OFF_F1    (OFF_HLN   + SZ_ACT)
#define LDATTN    196
#define OFF_ATTN  (OFF_F1    + SZ_ACT)          // 21*196 = 4116
#define LDDOT     52
#define OFF_DOTS  (OFF_ATTN  + NSLOT*LDATTN)    // 1092
#define OFF_INV   (OFF_DOTS  + NSLOT*LDDOT)     // 32
#define OFF_LNP   (OFF_INV   + 32)              // 4*256 LN params
#define OFF_RED   (OFF_LNP   + 1024)            // 4*1536 = 6144 reduction scratch
#define OFF_BUF   (OFF_RED   + 6144)            // B staging: 2 * 4 * 548
#define SBUF_SL   548                           // per-slice pitch (pad for banks)
#define SBUF_HALF (4*SBUF_SL)                   // 2192
#define SMEM_FLOATS (OFF_BUF + 2*SBUF_HALF)     // 55012
#define SMEM_BYTES  (SMEM_FLOATS*4)             // 220048 (< 227KB cap)

// ---------------- small helpers ----------------
__device__ __forceinline__ float warpSum(float v) {
    #pragma unroll
    for (int o = 16; o; o >>= 1) v += __shfl_xor_sync(0xffffffffu, v, o);
    return v;
}

__device__ __forceinline__ void cluster_sync_all() {
    asm volatile("barrier.cluster.arrive.aligned;\n\tbarrier.cluster.wait.aligned;" ::: "memory");
}

// packed fp32x2 FMA (sm_103a): acc = a*b + acc on two lanes at once
#define FMA2(acc, a, b) \
    asm("fma.rn.f32x2 %0, %1, %2, %0;" : "+l"(acc) : "l"(a), "l"(b))

__device__ __forceinline__ uint64_t pk2(float x) {
    uint64_t r; uint32_t u = __float_as_uint(x);
    asm("mov.b64 %0, {%1, %1};" : "=l"(r) : "r"(u));
    return r;
}
__device__ __forceinline__ float lo32(uint64_t v) { return __uint_as_float((uint32_t)v); }
__device__ __forceinline__ float hi32(uint64_t v) { return __uint_as_float((uint32_t)(v >> 32)); }

// ---------------- prep: slots0 + all weight transposes in ONE launch ----------
__global__ __launch_bounds__(256) void prep_kernel(
    const float* __restrict__ noise, const float* __restrict__ mu,
    const float* __restrict__ sg, float* __restrict__ slots,
    const float* __restrict__ Wq,  float* __restrict__ wqt,
    const float* __restrict__ W1,  float* __restrict__ w1t,
    const float* __restrict__ W2,  float* __restrict__ w2t,
    const float* __restrict__ Wih, float* __restrict__ wiht,
    const float* __restrict__ Whh, float* __restrict__ whht)
{
    int blk = blockIdx.x;
    int tid = threadIdx.x;
    if (blk < 672) {                       // slots0 = mu + sigma*noise
        int idx = blk * 256 + tid;
        int d = idx & 255;
        slots[idx] = mu[d] + sg[d] * noise[idx];
        return;
    }
    blk -= 672;
    const float* src; float* dst; int rows;
    if      (blk < 64)  { src = Wq;  dst = wqt;  rows = 256; }
    else if (blk < 128) { src = W1;  dst = w1t;  rows = 256; blk -= 64; }
    else if (blk < 192) { src = W2;  dst = w2t;  rows = 256; blk -= 128; }
    else if (blk < 384) { src = Wih; dst = wiht; rows = 768; blk -= 192; }
    else                { src = Whh; dst = whht; rows = 768; blk -= 384; }
    __shared__ float tile[32][33];
    int bx = blk & 7, by = blk >> 3;
    int lane = tid & 31, ty = tid >> 5;
    int x = bx * 32 + lane;
    int y0 = by * 32;
    for (int j = ty; j < 32; j += 8)
        tile[j][lane] = src[(size_t)(y0 + j) * 256 + x];
    __syncthreads();
    for (int j = ty; j < 32; j += 8)
        dst[(size_t)(bx * 32 + j) * rows + y0 + lane] = tile[lane][j];
}

// ---------------- per-row LayerNorm over D=256 (inputs path) ----------------
__global__ __launch_bounds__(256) void ln_kernel(const float* __restrict__ x,
                          const float* __restrict__ g,
                          const float* __restrict__ b,
                          float* __restrict__ y) {
    __shared__ float red[8];
    int row = blockIdx.x;
    int tid = threadIdx.x;
    size_t off = (size_t)row * DIM + tid;
    float v = x[off];
    float s = warpSum(v);
    if ((tid & 31) == 0) red[tid >> 5] = s;
    __syncthreads();
    float mean = (red[0]+red[1]+red[2]+red[3]+red[4]+red[5]+red[6]+red[7]) * (1.f/DIM);
    float d = v - mean;
    __syncthreads();
    float s2 = warpSum(d * d);
    if ((tid & 31) == 0) red[tid >> 5] = s2;
    __syncthreads();
    float var = (red[0]+red[1]+red[2]+red[3]+red[4]+red[5]+red[6]+red[7]) * (1.f/DIM);
    y[off] = d * rsqrtf(var + LN_EPS) * g[tid] + b[tid];
}

// ---------------- fused K/V projection (z selects K or V) ----------
// smem tiles stored K-MAJOR so the inner loop uses vectorized LDS.128.
#define BM 64
#define BN 64
#define BK 16
__global__ __launch_bounds__(256) void gemmkv_kernel(const float* __restrict__ A,
                            const float* __restrict__ Wk, const float* __restrict__ bk,
                            float* __restrict__ kb,
                            const float* __restrict__ Wv, const float* __restrict__ bv,
                            float* __restrict__ vb) {
    const int N = DIM, K = DIM;
    const float* W    = blockIdx.z ? Wv : Wk;
    const float* bias = blockIdx.z ? bv : bk;
    float*       C    = blockIdx.z ? vb : kb;
    __shared__ float As[BK][BM + 4];
    __shared__ float Bs[BK][BN + 4];
    int tid = threadIdx.x;
    int tx = tid & 15, ty = tid >> 4;
    int rowBase = blockIdx.y * BM;
    int colBase = blockIdx.x * BN;
    int lr = tid >> 2;
    int lk = (tid & 3) << 2;
    float acc[4][4] = {};
    for (int k0 = 0; k0 < K; k0 += BK) {
        float4 av = *reinterpret_cast<const float4*>(A + (size_t)(rowBase + lr) * K + k0 + lk);
        As[lk+0][lr] = av.x; As[lk+1][lr] = av.y; As[lk+2][lr] = av.z; As[lk+3][lr] = av.w;
        float4 bv4 = *reinterpret_cast<const float4*>(W + (size_t)(colBase + lr) * K + k0 + lk);
        Bs[lk+0][lr] = bv4.x; Bs[lk+1][lr] = bv4.y; Bs[lk+2][lr] = bv4.z; Bs[lk+3][lr] = bv4.w;
        __syncthreads();
        #pragma unroll
        for (int kk = 0; kk < BK; kk++) {
            float4 a = *reinterpret_cast<const float4*>(&As[kk][ty*4]);
            float4 b = *reinterpret_cast<const float4*>(&Bs[kk][tx*4]);
            acc[0][0] = fmaf(a.x, b.x, acc[0][0]); acc[0][1] = fmaf(a.x, b.y, acc[0][1]);
            acc[0][2] = fmaf(a.x, b.z, acc[0][2]); acc[0][3] = fmaf(a.x, b.w, acc[0][3]);
            acc[1][0] = fmaf(a.y, b.x, acc[1][0]); acc[1][1] = fmaf(a.y, b.y, acc[1][1]);
            acc[1][2] = fmaf(a.y, b.z, acc[1][2]); acc[1][3] = fmaf(a.y, b.w, acc[1][3]);
            acc[2][0] = fmaf(a.z, b.x, acc[2][0]); acc[2][1] = fmaf(a.z, b.y, acc[2][1]);
            acc[2][2] = fmaf(a.z, b.z, acc[2][2]); acc[2][3] = fmaf(a.z, b.w, acc[2][3]);
            acc[3][0] = fmaf(a.w, b.x, acc[3][0]); acc[3][1] = fmaf(a.w, b.y, acc[3][1]);
            acc[3][2] = fmaf(a.w, b.z, acc[3][2]); acc[3][3] = fmaf(a.w, b.w, acc[3][3]);
        }
        __syncthreads();
    }
    #pragma unroll
    for (int i = 0; i < 4; i++) {
        int r = rowBase + ty*4 + i;
        #pragma unroll
        for (int j = 0; j < 4; j++) {
            int c = colBase + tx*4 + j;
            C[(size_t)r * N + c] = acc[i][j] + bias[c];
        }
    }
}

// ============================================================================
// Persistent per-batch cluster kernel, 512 threads (16 warps, 4/SMSP for
// latency hiding; regs/thread halved vs 256-thread version to avoid the
// 253-reg spill cliff ncu exposed). fp32 f32x2 GEMMs, B staged through smem
// once (L2-dedup), double-buffered chunks. TRANS=1 transposes j-major keys
// during staging.
// Thread map: slice = tid>>7 (4 k-slices), cg = (tid&127)&15 -> 4 cols,
// rg = (tid&127)>>4 -> 3 rows. Tile 3x4 per thread.
// ============================================================================
template<int TRANS>
__device__ __forceinline__ void rb_gemm(
    const float* __restrict__ s_a, int lda, int kdim,
    float* __restrict__ s_red, float* __restrict__ s_buf,
    const float* __restrict__ B, int ldb,      // TRANS=0: k-major [k][ldb]; TRANS=1: [j][ldb]
    const float* __restrict__ bias, int ncols,
    float scale, int relu,
    const float* __restrict__ s_res, int res_off,
    const float* __restrict__ s_invp,
    float* __restrict__ g_out, int g_ld,
    float* __restrict__ s_out, int s_ld)
{
    int tid = threadIdx.x;
    int slice = tid >> 7;
    int t  = tid & 127;
    int cg = t & 15;
    int rg = t >> 4;
    int ksl = kdim >> 2;
    int nchunk = ksl >> 3;
    int c0 = cg * 4;
    int r0 = rg * 3;
    int kbase = slice * ksl;

    // staging thread mapping (512 threads, 1 float4 each)
    int srow  = tid >> 4;        // TRANS=0: 0..31 staged row id
    int st_s  = srow >> 3;       //   slice of staged row
    int st_kk = srow & 7;        //   local k row
    int st_c  = (tid & 15) * 4;  //   col offset
    int jrow  = tid & 63;        // TRANS=1: j index (valid < ncols)
    int part  = tid >> 6;        //   0..7
    int tr_s  = part >> 1;       //   slice
    int tr_dq = part & 1;        //   d quad

    uint64_t acc2[3][2] = {};
    float4 ra;

    // ---- load chunk 0 ----
    if (TRANS == 0) {
        int k = st_s * ksl + st_kk;
        ra = *reinterpret_cast<const float4*>(B + (size_t)k * ldb + st_c);
    } else if (jrow < ncols) {
        int d = tr_s * ksl + tr_dq * 4;
        ra = *reinterpret_cast<const float4*>(B + (size_t)jrow * ldb + d);
    }
    // ---- store chunk 0 ----
    if (TRANS == 0) {
        *reinterpret_cast<float4*>(s_buf + st_s*SBUF_SL + st_kk*68 + st_c) = ra;
    } else if (jrow < ncols) {
        float* base = s_buf + tr_s*SBUF_SL + tr_dq*4*68;
        base[0*68 + jrow] = ra.x; base[1*68 + jrow] = ra.y;
        base[2*68 + jrow] = ra.z; base[3*68 + jrow] = ra.w;
    }
    __syncthreads();

    int p = 0;
    for (int ch = 0; ch < nchunk; ch++) {
        if (ch + 1 < nchunk) {               // prefetch next chunk into regs
            int c8 = (ch + 1) * 8;
            if (TRANS == 0) {
                int k = st_s * ksl + c8 + st_kk;
                ra = *reinterpret_cast<const float4*>(B + (size_t)k * ldb + st_c);
            } else if (jrow < ncols) {
                int d = tr_s * ksl + c8 + tr_dq * 4;
                ra = *reinterpret_cast<const float4*>(B + (size_t)jrow * ldb + d);
            }
        }
        // compute chunk ch from buf p
        const float* bb = s_buf + p * SBUF_HALF + slice * SBUF_SL;
        int ka = kbase + ch * 8;
        #pragma unroll
        for (int kk4 = 0; kk4 < 2; kk4++) {
            ulonglong2 b0 = *reinterpret_cast<const ulonglong2*>(bb + (kk4*4+0)*68 + c0);
            ulonglong2 b1 = *reinterpret_cast<const ulonglong2*>(bb + (kk4*4+1)*68 + c0);
            ulonglong2 b2 = *reinterpret_cast<const ulonglong2*>(bb + (kk4*4+2)*68 + c0);
            ulonglong2 b3 = *reinterpret_cast<const ulonglong2*>(bb + (kk4*4+3)*68 + c0);
            #pragma unroll
            for (int r = 0; r < 3; r++) {
                float4 a = *reinterpret_cast<const float4*>(s_a + (r0 + r)*lda + ka + kk4*4);
                uint64_t ax = pk2(a.x), ay = pk2(a.y), az = pk2(a.z), aw = pk2(a.w);
                FMA2(acc2[r][0], ax, b0.x); FMA2(acc2[r][1], ax, b0.y);
                FMA2(acc2[r][0], ay, b1.x); FMA2(acc2[r][1], ay, b1.y);
                FMA2(acc2[r][0], az, b2.x); FMA2(acc2[r][1], az, b2.y);
                FMA2(acc2[r][0], aw, b3.x); FMA2(acc2[r][1], aw, b3.y);
            }
        }
        if (ch + 1 < nchunk) {               // store next into other buffer
            float* nb = s_buf + (1 - p) * SBUF_HALF;
            if (TRANS == 0) {
                *reinterpret_cast<float4*>(nb + st_s*SBUF_SL + st_kk*68 + st_c) = ra;
            } else if (jrow < ncols) {
                float* base = nb + tr_s*SBUF_SL + tr_dq*4*68;
                base[0*68 + jrow] = ra.x; base[1*68 + jrow] = ra.y;
                base[2*68 + jrow] = ra.z; base[3*68 + jrow] = ra.w;
            }
        }
        __syncthreads();
        p ^= 1;
    }

    // partial-sum reduction across the 4 k-slices + fused epilogue
    #pragma unroll
    for (int r = 0; r < 3; r++) {
        float4 o;
        o.x = lo32(acc2[r][0]); o.y = hi32(acc2[r][0]);
        o.z = lo32(acc2[r][1]); o.w = hi32(acc2[r][1]);
        *reinterpret_cast<float4*>(s_red + slice*1536 + (r0 + r)*64 + c0) = o;
    }
    __syncthreads();
    #pragma unroll
    for (int u = 0; u < 3; u++) {
        int o = u*TPB + tid;
        int row = o >> 6, col = o & 63;
        if (row < NSLOT && col < ncols) {
            float v = s_red[o] + s_red[1536+o] + s_red[3072+o] + s_red[4608+o];
            float rv;
            if (s_invp) {
                rv = v * s_invp[row];
            } else {
                rv = v * scale + (bias ? bias[col] : 0.f);
                if (relu) rv = fmaxf(rv, 0.f);
                if (s_res) rv += s_res[row*LDA + res_off + col];
            }
            if (g_out) g_out[(size_t)row * g_ld + col] = rv;
            if (s_out) s_out[row * s_ld + col] = rv;
        }
    }
    __syncthreads();
}

// per-row LN of smem 21x256 (warp per row), params from smem
__device__ __forceinline__ void ln_rows(const float* __restrict__ s_src,
                                        float* __restrict__ s_dst,
                                        const float* __restrict__ gg,
                                        const float* __restrict__ bb)
{
    int tid = threadIdx.x;
    int w = tid >> 5, lane = tid & 31;
    for (int row = w; row < NSLOT; row += 16) {
        const float* src = s_src + row*LDA;
        float v[8]; float s = 0.f;
        #pragma unroll
        for (int m = 0; m < 8; m++) { v[m] = src[lane + 32*m]; s += v[m]; }
        s = warpSum(s);
        float mean = s * (1.f/256.f);
        float s2 = 0.f;
        #pragma unroll
        for (int m = 0; m < 8; m++) { float d = v[m]-mean; s2 += d*d; }
        s2 = warpSum(s2);
        float inv = rsqrtf(s2 * (1.f/256.f) + LN_EPS);
        float* dst = s_dst + row*LDA;
        #pragma unroll
        for (int m = 0; m < 8; m++) {
            int d = lane + 32*m;
            dst[d] = (v[m]-mean) * inv * gg[d] + bb[d];
        }
    }
}

// load 21x256 global (ld 256) -> smem (ld LDA)
__device__ __forceinline__ void load_act(float* __restrict__ s_dst,
                                         const float* __restrict__ g_src)
{
    int tid = threadIdx.x;
    for (int i = tid; i < NSLOT*64; i += TPB) {
        int row = i >> 6, c4 = i & 63;
        *reinterpret_cast<float4*>(&s_dst[row*LDA + c4*4]) =
            *reinterpret_cast<const float4*>(&g_src[(size_t)row*256 + c4*4]);
    }
}

__global__ void __cluster_dims__(4,1,1) __launch_bounds__(TPB,1)
slot_iter_kernel(const float* __restrict__ kb, const float* __restrict__ vb,
                 float* __restrict__ slots_g, float* __restrict__ q_g,
                 float* __restrict__ attn_g, float* __restrict__ upd_g,
                 float* __restrict__ gi_g, float* __restrict__ gh_g,
                 float* __restrict__ h_g, float* __restrict__ f1_g,
                 const float* __restrict__ Wqt, const float* __restrict__ bq,
                 const float* __restrict__ W1t, const float* __restrict__ b1,
                 const float* __restrict__ W2t, const float* __restrict__ b2,
                 const float* __restrict__ Wiht, const float* __restrict__ b_ih,
                 const float* __restrict__ Whht, const float* __restrict__ b_hh,
                 const float* __restrict__ g_sl, const float* __restrict__ be_sl,
                 const float* __restrict__ g_ff, const float* __restrict__ be_ff,
                 float* __restrict__ out_attn)
{
    extern __shared__ float sm[];
    int tid = threadIdx.x;
    int b = blockIdx.x >> 2;
    int r = blockIdx.x & 3;

    float* s_slots = sm + OFF_SLOTS;
    float* s_sln   = sm + OFF_SLN;
    float* s_q     = sm + OFF_Q;
    float* s_upd   = sm + OFF_UPD;
    float* s_h     = sm + OFF_H;
    float* s_hln   = sm + OFF_HLN;
    float* s_f1    = sm + OFF_F1;
    float* s_attn  = sm + OFF_ATTN;
    float* s_dots  = sm + OFF_DOTS;
    float* s_inv   = sm + OFF_INV;
    float* s_lnp   = sm + OFF_LNP;
    float* s_red   = sm + OFF_RED;
    float* s_buf   = sm + OFF_BUF;

    float* slots_b = slots_g + (size_t)b * NSLOT * 256;
    float* q_b     = q_g     + (size_t)b * NSLOT * 256;
    float* attn_b  = attn_g  + (size_t)b * NSLOT * HW;
    float* upd_b   = upd_g   + (size_t)b * NSLOT * 256;
    float* gi_b    = gi_g    + (size_t)b * NSLOT * 768;
    float* gh_b    = gh_g    + (size_t)b * NSLOT * 768;
    float* h_b     = h_g     + (size_t)b * NSLOT * 256;
    float* f1_b    = f1_g    + (size_t)b * NSLOT * 256;

    if (tid < 256) {
        s_lnp[tid]       = g_sl[tid];
        s_lnp[tid + 256] = be_sl[tid];
        s_lnp[tid + 512] = g_ff[tid];
        s_lnp[tid + 768] = be_ff[tid];
    }
    load_act(s_slots, slots_b);
    __syncthreads();

    for (int f = 0; f < NFRM; f++) {
        const float* kf = kb + (size_t)(b*NFRM + f) * HW * 256;   // [j][d]
        const float* vf = vb + (size_t)(b*NFRM + f) * HW * 256;   // [j][d]
        for (int it = 0; it < 3; it++) {
            // ---- A: LN(slots) -> q slice ----
            ln_rows(s_slots, s_sln, s_lnp, s_lnp + 256);
            __syncthreads();
            rb_gemm<0>(s_sln, LDA, 256, s_red, s_buf, Wqt + r*64, 256, bq + r*64,
                       64, 1.f, 0, nullptr, 0, nullptr, q_b + r*64, 256, nullptr, 0);
            cluster_sync_all();
            load_act(s_q, q_b);
            __syncthreads();

            // ---- B1: dots slice (48 j-cols, transpose-staged keys) + softmax ----
            rb_gemm<1>(s_q, LDA, 256, s_red, s_buf, kf + (size_t)(r*48)*256, 256, nullptr,
                       48, SCALE, 0, nullptr, 0, nullptr, nullptr, 0, s_dots, LDDOT);
            if (tid < 48) {
                int j = tid;
                float m = -1e30f;
                #pragma unroll
                for (int i = 0; i < NSLOT; i++) m = fmaxf(m, s_dots[i*LDDOT + j]);
                float e[NSLOT]; float sum = 0.f;
                #pragma unroll
                for (int i = 0; i < NSLOT; i++) { e[i] = expf(s_dots[i*LDDOT + j] - m); sum += e[i]; }
                float inv = 1.f / sum;
                int jg = r*48 + j;
                float* oa = out_attn + ((size_t)(b*NFRM + f) * NSLOT) * HW;
                #pragma unroll
                for (int i = 0; i < NSLOT; i++) {
                    float a = e[i]*inv + ATTN_EPS;
                    attn_b[(size_t)i*HW + jg] = a;
                    if (it == 2) oa[(size_t)i*HW + jg] = a;
                }
            }
            cluster_sync_all();

            // ---- B2: row-normalize + updates slice ----
            for (int i = tid; i < NSLOT*48; i += TPB) {
                int row = i / 48, c4 = i % 48;
                *reinterpret_cast<float4*>(&s_attn[row*LDATTN + c4*4]) =
                    *reinterpret_cast<const float4*>(&attn_b[(size_t)row*HW + c4*4]);
            }
            __syncthreads();
            {
                int w = tid >> 5, lane = tid & 31;
                for (int row = w; row < NSLOT; row += 16) {
                    float s = 0.f;
                    for (int j = lane; j < HW; j += 32) s += s_attn[row*LDATTN + j];
                    s = warpSum(s);
                    if (lane == 0) s_inv[row] = 1.f / s;
                }
            }
            __syncthreads();
            rb_gemm<0>(s_attn, LDATTN, 192, s_red, s_buf, vf + r*64, 256, nullptr,
                       64, 1.f, 0, nullptr, 0, s_inv, upd_b + r*64, 256, nullptr, 0);
            cluster_sync_all();
            load_act(s_upd, upd_b);
            __syncthreads();

            // ---- C: GRU gemms (gi from upd, gh from raw slots), 192 cols each ----
            #pragma unroll
            for (int t = 0; t < 3; t++) {
                int cb = r*192 + t*64;
                rb_gemm<0>(s_upd, LDA, 256, s_red, s_buf, Wiht + cb, 768, b_ih + cb,
                           64, 1.f, 0, nullptr, 0, nullptr, gi_b + cb, 768, nullptr, 0);
                rb_gemm<0>(s_slots, LDA, 256, s_red, s_buf, Whht + cb, 768, b_hh + cb,
                           64, 1.f, 0, nullptr, 0, nullptr, gh_b + cb, 768, nullptr, 0);
            }
            cluster_sync_all();

            // ---- gate ----
            for (int idx = tid; idx < NSLOT*64; idx += TPB) {
                int i = idx >> 6; int d = r*64 + (idx & 63);
                const float* gir = gi_b + (size_t)i*768;
                const float* ghr = gh_b + (size_t)i*768;
                float ir = gir[d], iz = gir[d+256], inn = gir[d+512];
                float hr = ghr[d], hz = ghr[d+256], hn  = ghr[d+512];
                float hp = s_slots[i*LDA + d];
                float rr = 1.f / (1.f + expf(-(ir + hr)));
                float zz = 1.f / (1.f + expf(-(iz + hz)));
                float nn = tanhf(inn + rr * hn);
                h_b[(size_t)i*256 + d] = (1.f - zz) * nn + zz * hp;
            }
            cluster_sync_all();
            load_act(s_h, h_b);
            __syncthreads();
            ln_rows(s_h, s_hln, s_lnp + 512, s_lnp + 768);
            __syncthreads();

            // ---- D: MLP ----
            rb_gemm<0>(s_hln, LDA, 256, s_red, s_buf, W1t + r*64, 256, b1 + r*64,
                       64, 1.f, 1, nullptr, 0, nullptr, f1_b + r*64, 256, nullptr, 0);
            cluster_sync_all();
            load_act(s_f1, f1_b);
            __syncthreads();
            rb_gemm<0>(s_f1, LDA, 256, s_red, s_buf, W2t + r*64, 256, b2 + r*64,
                       64, 1.f, 0, s_h, r*64, nullptr, slots_b + r*64, 256, nullptr, 0);
            cluster_sync_all();
            load_act(s_slots, slots_b);
            __syncthreads();
        }
    }
}

// ---------------- final slots copy (first 20 of 21 slots) ----------------
__global__ void copy_slots_kernel(const float* __restrict__ slots, float* __restrict__ out) {
    int idx = blockIdx.x * 256 + threadIdx.x;
    int d = idx & 255;
    int s = (idx >> 8) % NACT;
    int b = idx / (NACT * DIM);
    out[idx] = slots[((size_t)(b * NSLOT + s) << 8) + d];
}

// ---------------- launch ----------------
extern "C" void kernel_launch(void* const* d_in, const int* in_sizes, int n_in,
                              void* d_out, int out_size) {
    const float* inputs = (const float*)d_in[0];
    const float* noise  = (const float*)d_in[1];
    const float* mu     = (const float*)d_in[2];
    const float* sigma  = (const float*)d_in[3];
    const float* Wq = (const float*)d_in[4];  const float* bq = (const float*)d_in[5];
    const float* Wk = (const float*)d_in[6];  const float* bk = (const float*)d_in[7];
    const float* Wv = (const float*)d_in[8];  const float* bv = (const float*)d_in[9];
    const float* W1 = (const float*)d_in[10]; const float* b1 = (const float*)d_in[11];
    const float* W2 = (const float*)d_in[12]; const float* b2 = (const float*)d_in[13];
    const float* W_ih = (const float*)d_in[14]; const float* b_ih = (const float*)d_in[15];
    const float* W_hh = (const float*)d_in[16]; const float* b_hh = (const float*)d_in[17];
    const float* g_in_p = (const float*)d_in[18]; const float* be_in = (const float*)d_in[19];
    const float* g_sl_p = (const float*)d_in[20]; const float* be_sl = (const float*)d_in[21];
    const float* g_ff_p = (const float*)d_in[22]; const float* be_ff = (const float*)d_in[23];
    float* out = (float*)d_out;

    float *xn, *kb, *vb, *slots, *qb, *attnO, *upd, *gi, *gh, *hb, *f1;
    float *wqt, *w1t, *w2t, *wiht, *whht;
    cudaGetSymbolAddress((void**)&xn,    g_xn);
    cudaGetSymbolAddress((void**)&kb,    g_k);
    cudaGetSymbolAddress((void**)&vb,    g_v);
    cudaGetSymbolAddress((void**)&slots, g_slots);
    cudaGetSymbolAddress((void**)&qb,    g_q);
    cudaGetSymbolAddress((void**)&attnO, g_attn);
    cudaGetSymbolAddress((void**)&upd,   g_upd);
    cudaGetSymbolAddress((void**)&gi,    g_gi);
    cudaGetSymbolAddress((void**)&gh,    g_gh);
    cudaGetSymbolAddress((void**)&hb,    g_h);
    cudaGetSymbolAddress((void**)&f1,    g_f1);
    cudaGetSymbolAddress((void**)&wqt,   g_wqt);
    cudaGetSymbolAddress((void**)&w1t,   g_w1t);
    cudaGetSymbolAddress((void**)&w2t,   g_w2t);
    cudaGetSymbolAddress((void**)&wiht,  g_wiht);
    cudaGetSymbolAddress((void**)&whht,  g_whht);

    cudaFuncSetAttribute(slot_iter_kernel,
                         cudaFuncAttributeMaxDynamicSharedMemorySize, SMEM_BYTES);

    // 1: slots0 + all weight transposes
    prep_kernel<<<672 + 64*3 + 192*2, 256>>>(noise, mu, sigma, slots,
                                             Wq, wqt, W1, w1t, W2, w2t,
                                             W_ih, wiht, W_hh, whht);
    // 2: LN(inputs)
    ln_kernel<<<ROWS_KV, 256>>>(inputs, g_in_p, be_in, xn);
    // 3: fused K/V projections
    dim3 gkv(DIM / BN, ROWS_KV / BM, 2);
    gemmkv_kernel<<<gkv, 256>>>(xn, Wk, bk, kb, Wv, bv, vb);
    // 4: persistent iteration kernel (profiled launch)
    float* attn_out = out + SLOTS_OUT_SIZE;
    slot_iter_kernel<<<BATCH * 4, TPB, SMEM_BYTES>>>(
        kb, vb, slots, qb, attnO, upd, gi, gh, hb, f1,
        wqt, bq, w1t, b1, w2t, b2, wiht, b_ih, whht, b_hh,
        g_sl_p, be_sl, g_ff_p, be_ff, attn_out);
    // 5: output copy
    copy_slots_kernel<<<SLOTS_OUT_SIZE / 256, 256>>>(slots, out);
}

// round 14
// speedup vs baseline: 1.6001x; 1.6001x over previous
#include <cuda_runtime.h>
#include <cuda_bf16.h>
#include <cstdint>
#include <math.h>

// ---------------- problem constants ----------------
#define BATCH 32
#define NFRM  16
#define HW    192        // H*W = 8*24
#define DIM   256
#define NSLOT 21
#define NACT  20
#define ROWS_KV (BATCH*NFRM*HW)   // 98304
#define ROWS_S  (BATCH*NSLOT)     // 672
#define SLOTS_OUT_SIZE (BATCH*NACT*DIM)  // 163840
#define ATTN_EPS 1e-8f
#define LN_EPS   1e-5f
#define SCALE    0.0625f   // 256^-0.5

// ---------------- scratch (static device globals; no allocs) ----------------
__device__ float g_xn  [ROWS_KV*DIM];
__device__ float g_k   [ROWS_KV*DIM];
__device__ float g_v   [ROWS_KV*DIM];
__device__ float g_slots[ROWS_S*DIM];
__device__ float g_q   [ROWS_S*DIM];
__device__ float g_attn[BATCH*NSLOT*HW];
__device__ float g_upd [ROWS_S*DIM];
__device__ float g_h   [ROWS_S*DIM];
__device__ float g_f1  [ROWS_S*DIM];
// k-major transposed weights [k=256][n]
__device__ float g_wqt [DIM*DIM];
__device__ float g_w1t [DIM*DIM];
__device__ float g_w2t [DIM*DIM];
__device__ float g_wiht[DIM*3*DIM];
__device__ float g_whht[DIM*3*DIM];

// ---------------- smem layout (floats) for persistent kernel ----------------
// GEMMs read A rows up to 23 (rows >= 21 are discarded garbage); every A
// buffer is followed by enough other smem that overshoot reads stay inside
// the dynamic allocation.
#define LDA     260            // row stride for 21x256 activation buffers
#define SZ_ACT  (NSLOT*LDA)    // 5460
#define OFF_SLOTS 0
#define OFF_SLN   (OFF_SLOTS + SZ_ACT)   // also reused as s_gi (21 x 192, ld 196)
#define OFF_Q     (OFF_SLN   + SZ_ACT)   // also reused as s_gh
#define OFF_UPD   (OFF_Q     + SZ_ACT)
#define OFF_H     (OFF_UPD   + SZ_ACT)
#define OFF_HLN   (OFF_H     + SZ_ACT)
#define OFF_F1    (OFF_HLN   + SZ_ACT)
#define LDATTN    196
#define OFF_ATTN  (OFF_F1    + SZ_ACT)          // 21*196 = 4116
#define LDDOT     52
#define OFF_DOTS  (OFF_ATTN  + NSLOT*LDATTN)    // 1092
#define OFF_INV   (OFF_DOTS  + NSLOT*LDDOT)     // 32
#define OFF_LNP   (OFF_INV   + 32)              // 4*256 LN params
#define OFF_RED   (OFF_LNP   + 1024)            // 4*1536 = 6144 reduction scratch
#define OFF_BUF   (OFF_RED   + 6144)            // B staging: 2 * 4 * 548
#define SBUF_SL   548                           // per-slice pitch (pad for banks)
#define SBUF_HALF (4*SBUF_SL)                   // 2192
#define SMEM_FLOATS (OFF_BUF + 2*SBUF_HALF)     // 55012
#define SMEM_BYTES  (SMEM_FLOATS*4)             // 220048 (< 227KB cap)
#define LDG3      196                           // gi/gh smem row stride

// ---------------- small helpers ----------------
__device__ __forceinline__ float warpSum(float v) {
    #pragma unroll
    for (int o = 16; o; o >>= 1) v += __shfl_xor_sync(0xffffffffu, v, o);
    return v;
}

__device__ __forceinline__ void cluster_sync_all() {
    asm volatile("barrier.cluster.arrive.aligned;\n\tbarrier.cluster.wait.aligned;" ::: "memory");
}

// packed fp32x2 FMA (sm_103a): acc = a*b + acc on two lanes at once
#define FMA2(acc, a, b) \
    asm("fma.rn.f32x2 %0, %1, %2, %0;" : "+l"(acc) : "l"(a), "l"(b))

__device__ __forceinline__ uint64_t pk2(float x) {
    uint64_t r; uint32_t u = __float_as_uint(x);
    asm("mov.b64 %0, {%1, %1};" : "=l"(r) : "r"(u));
    return r;
}
__device__ __forceinline__ float lo32(uint64_t v) { return __uint_as_float((uint32_t)v); }
__device__ __forceinline__ float hi32(uint64_t v) { return __uint_as_float((uint32_t)(v >> 32)); }

// ---------------- prep: slots0 + all weight transposes in ONE launch ----------
__global__ __launch_bounds__(256) void prep_kernel(
    const float* __restrict__ noise, const float* __restrict__ mu,
    const float* __restrict__ sg, float* __restrict__ slots,
    const float* __restrict__ Wq,  float* __restrict__ wqt,
    const float* __restrict__ W1,  float* __restrict__ w1t,
    const float* __restrict__ W2,  float* __restrict__ w2t,
    const float* __restrict__ Wih, float* __restrict__ wiht,
    const float* __restrict__ Whh, float* __restrict__ whht)
{
    int blk = blockIdx.x;
    int tid = threadIdx.x;
    if (blk < 672) {                       // slots0 = mu + sigma*noise
        int idx = blk * 256 + tid;
        int d = idx & 255;
        slots[idx] = mu[d] + sg[d] * noise[idx];
        return;
    }
    blk -= 672;
    const float* src; float* dst; int rows;
    if      (blk < 64)  { src = Wq;  dst = wqt;  rows = 256; }
    else if (blk < 128) { src = W1;  dst = w1t;  rows = 256; blk -= 64; }
    else if (blk < 192) { src = W2;  dst = w2t;  rows = 256; blk -= 128; }
    else if (blk < 384) { src = Wih; dst = wiht; rows = 768; blk -= 192; }
    else                { src = Whh; dst = whht; rows = 768; blk -= 384; }
    __shared__ float tile[32][33];
    int bx = blk & 7, by = blk >> 3;
    int lane = tid & 31, ty = tid >> 5;
    int x = bx * 32 + lane;
    int y0 = by * 32;
    for (int j = ty; j < 32; j += 8)
        tile[j][lane] = src[(size_t)(y0 + j) * 256 + x];
    __syncthreads();
    for (int j = ty; j < 32; j += 8)
        dst[(size_t)(bx * 32 + j) * rows + y0 + lane] = tile[lane][j];
}

// ---------------- per-row LayerNorm over D=256 (inputs path) ----------------
__global__ __launch_bounds__(256) void ln_kernel(const float* __restrict__ x,
                          const float* __restrict__ g,
                          const float* __restrict__ b,
                          float* __restrict__ y) {
    __shared__ float red[8];
    int row = blockIdx.x;
    int tid = threadIdx.x;
    size_t off = (size_t)row * DIM + tid;
    float v = x[off];
    float s = warpSum(v);
    if ((tid & 31) == 0) red[tid >> 5] = s;
    __syncthreads();
    float mean = (red[0]+red[1]+red[2]+red[3]+red[4]+red[5]+red[6]+red[7]) * (1.f/DIM);
    float d = v - mean;
    __syncthreads();
    float s2 = warpSum(d * d);
    if ((tid & 31) == 0) red[tid >> 5] = s2;
    __syncthreads();
    float var = (red[0]+red[1]+red[2]+red[3]+red[4]+red[5]+red[6]+red[7]) * (1.f/DIM);
    y[off] = d * rsqrtf(var + LN_EPS) * g[tid] + b[tid];
}

// ---------------- fused K/V projection (z selects K or V) ----------
// smem tiles stored K-MAJOR so the inner loop uses vectorized LDS.128.
#define BM 64
#define BN 64
#define BK 16
__global__ __launch_bounds__(256) void gemmkv_kernel(const float* __restrict__ A,
                            const float* __restrict__ Wk, const float* __restrict__ bk,
                            float* __restrict__ kb,
                            const float* __restrict__ Wv, const float* __restrict__ bv,
                            float* __restrict__ vb) {
    const int N = DIM, K = DIM;
    const float* W    = blockIdx.z ? Wv : Wk;
    const float* bias = blockIdx.z ? bv : bk;
    float*       C    = blockIdx.z ? vb : kb;
    __shared__ float As[BK][BM + 4];
    __shared__ float Bs[BK][BN + 4];
    int tid = threadIdx.x;
    int tx = tid & 15, ty = tid >> 4;
    int rowBase = blockIdx.y * BM;
    int colBase = blockIdx.x * BN;
    int lr = tid >> 2;
    int lk = (tid & 3) << 2;
    float acc[4][4] = {};
    for (int k0 = 0; k0 < K; k0 += BK) {
        float4 av = *reinterpret_cast<const float4*>(A + (size_t)(rowBase + lr) * K + k0 + lk);
        As[lk+0][lr] = av.x; As[lk+1][lr] = av.y; As[lk+2][lr] = av.z; As[lk+3][lr] = av.w;
        float4 bv4 = *reinterpret_cast<const float4*>(W + (size_t)(colBase + lr) * K + k0 + lk);
        Bs[lk+0][lr] = bv4.x; Bs[lk+1][lr] = bv4.y; Bs[lk+2][lr] = bv4.z; Bs[lk+3][lr] = bv4.w;
        __syncthreads();
        #pragma unroll
        for (int kk = 0; kk < BK; kk++) {
            float4 a = *reinterpret_cast<const float4*>(&As[kk][ty*4]);
            float4 b = *reinterpret_cast<const float4*>(&Bs[kk][tx*4]);
            acc[0][0] = fmaf(a.x, b.x, acc[0][0]); acc[0][1] = fmaf(a.x, b.y, acc[0][1]);
            acc[0][2] = fmaf(a.x, b.z, acc[0][2]); acc[0][3] = fmaf(a.x, b.w, acc[0][3]);
            acc[1][0] = fmaf(a.y, b.x, acc[1][0]); acc[1][1] = fmaf(a.y, b.y, acc[1][1]);
            acc[1][2] = fmaf(a.y, b.z, acc[1][2]); acc[1][3] = fmaf(a.y, b.w, acc[1][3]);
            acc[2][0] = fmaf(a.z, b.x, acc[2][0]); acc[2][1] = fmaf(a.z, b.y, acc[2][1]);
            acc[2][2] = fmaf(a.z, b.z, acc[2][2]); acc[2][3] = fmaf(a.z, b.w, acc[2][3]);
            acc[3][0] = fmaf(a.w, b.x, acc[3][0]); acc[3][1] = fmaf(a.w, b.y, acc[3][1]);
            acc[3][2] = fmaf(a.w, b.z, acc[3][2]); acc[3][3] = fmaf(a.w, b.w, acc[3][3]);
        }
        __syncthreads();
    }
    #pragma unroll
    for (int i = 0; i < 4; i++) {
        int r = rowBase + ty*4 + i;
        #pragma unroll
        for (int j = 0; j < 4; j++) {
            int c = colBase + tx*4 + j;
            C[(size_t)r * N + c] = acc[i][j] + bias[c];
        }
    }
}

// ============================================================================
// Persistent per-batch cluster kernel (256 threads — R10 winner config).
// Register-blocked fp32 GEMMs with fma.rn.f32x2; B staged cooperatively
// through smem once (L2-dedup), double-buffered chunks. TRANS=1 transposes
// j-major keys during staging. GRU columns remapped so the gate is
// rank-local: gi/gh stay in smem, no cluster sync / global traffic for them.
// ============================================================================
template<int TRANS>
__device__ __forceinline__ void rb_gemm(
    const float* __restrict__ s_a, int lda, int kdim,
    float* __restrict__ s_red, float* __restrict__ s_buf,
    const float* __restrict__ B, int ldb,      // TRANS=0: k-major [k][ldb]; TRANS=1: [j][ldb]
    const float* __restrict__ bias, int ncols,
    float scale, int relu,
    const float* __restrict__ s_res, int res_off,
    const float* __restrict__ s_invp,
    float* __restrict__ g_out, int g_ld,
    float* __restrict__ s_out, int s_ld)
{
    int tid = threadIdx.x;
    int slice = tid >> 6;
    int t  = tid & 63;
    int cg = t & 15;
    int rg = t >> 4;
    int ksl = kdim >> 2;
    int nchunk = ksl >> 3;
    int c0 = cg * 4;
    int r0 = rg * 6;
    int kbase = slice * ksl;

    // staging thread mapping
    int srow  = tid >> 3;        // 0..31
    int c4    = tid & 7;
    int st_s  = srow >> 3;       // TRANS=0: slice of staged row
    int st_kk = srow & 7;        // TRANS=0: local k row
    int st_c  = c4 * 8;          // TRANS=0: col offset (2 float4)
    int tr_s  = c4 >> 1;         // TRANS=1: slice
    int tr_dq = c4 & 1;          // TRANS=1: d quad

    uint64_t acc2[6][2] = {};
    float4 ra0, ra1;

    // ---- load + store chunk 0 ----
    if (TRANS == 0) {
        int k = st_s * ksl + st_kk;
        ra0 = *reinterpret_cast<const float4*>(B + (size_t)k * ldb + st_c);
        ra1 = *reinterpret_cast<const float4*>(B + (size_t)k * ldb + st_c + 4);
    } else {
        int d = tr_s * ksl + tr_dq * 4;
        ra0 = *reinterpret_cast<const float4*>(B + (size_t)srow * ldb + d);
        if (srow + 32 < ncols)
            ra1 = *reinterpret_cast<const float4*>(B + (size_t)(srow + 32) * ldb + d);
    }
    {
        float* bb = s_buf;
        if (TRANS == 0) {
            *reinterpret_cast<float4*>(bb + st_s*SBUF_SL + st_kk*68 + st_c)     = ra0;
            *reinterpret_cast<float4*>(bb + st_s*SBUF_SL + st_kk*68 + st_c + 4) = ra1;
        } else {
            float* base = bb + tr_s*SBUF_SL + tr_dq*4*68;
            base[0*68 + srow] = ra0.x; base[1*68 + srow] = ra0.y;
            base[2*68 + srow] = ra0.z; base[3*68 + srow] = ra0.w;
            int j1 = srow + 32;
            if (j1 < ncols) {
                base[0*68 + j1] = ra1.x; base[1*68 + j1] = ra1.y;
                base[2*68 + j1] = ra1.z; base[3*68 + j1] = ra1.w;
            }
        }
    }
    __syncthreads();

    int p = 0;
    for (int ch = 0; ch < nchunk; ch++) {
        if (ch + 1 < nchunk) {               // prefetch next chunk into regs
            int c8 = (ch + 1) * 8;
            if (TRANS == 0) {
                int k = st_s * ksl + c8 + st_kk;
                ra0 = *reinterpret_cast<const float4*>(B + (size_t)k * ldb + st_c);
                ra1 = *reinterpret_cast<const float4*>(B + (size_t)k * ldb + st_c + 4);
            } else {
                int d = tr_s * ksl + c8 + tr_dq * 4;
                ra0 = *reinterpret_cast<const float4*>(B + (size_t)srow * ldb + d);
                if (srow + 32 < ncols)
                    ra1 = *reinterpret_cast<const float4*>(B + (size_t)(srow + 32) * ldb + d);
            }
        }
        // compute chunk ch from buf p
        const float* bb = s_buf + p * SBUF_HALF + slice * SBUF_SL;
        int ka = kbase + ch * 8;
        #pragma unroll
        for (int kk4 = 0; kk4 < 2; kk4++) {
            ulonglong2 b0 = *reinterpret_cast<const ulonglong2*>(bb + (kk4*4+0)*68 + c0);
            ulonglong2 b1 = *reinterpret_cast<const ulonglong2*>(bb + (kk4*4+1)*68 + c0);
            ulonglong2 b2 = *reinterpret_cast<const ulonglong2*>(bb + (kk4*4+2)*68 + c0);
            ulonglong2 b3 = *reinterpret_cast<const ulonglong2*>(bb + (kk4*4+3)*68 + c0);
            #pragma unroll
            for (int r = 0; r < 6; r++) {
                float4 a = *reinterpret_cast<const float4*>(s_a + (r0 + r)*lda + ka + kk4*4);
                uint64_t ax = pk2(a.x), ay = pk2(a.y), az = pk2(a.z), aw = pk2(a.w);
                FMA2(acc2[r][0], ax, b0.x); FMA2(acc2[r][1], ax, b0.y);
                FMA2(acc2[r][0], ay, b1.x); FMA2(acc2[r][1], ay, b1.y);
                FMA2(acc2[r][0], az, b2.x); FMA2(acc2[r][1], az, b2.y);
                FMA2(acc2[r][0], aw, b3.x); FMA2(acc2[r][1], aw, b3.y);
            }
        }
        if (ch + 1 < nchunk) {               // store next into other buffer
            float* nb = s_buf + (1 - p) * SBUF_HALF;
            if (TRANS == 0) {
                *reinterpret_cast<float4*>(nb + st_s*SBUF_SL + st_kk*68 + st_c)     = ra0;
                *reinterpret_cast<float4*>(nb + st_s*SBUF_SL + st_kk*68 + st_c + 4) = ra1;
            } else {
                float* base = nb + tr_s*SBUF_SL + tr_dq*4*68;
                base[0*68 + srow] = ra0.x; base[1*68 + srow] = ra0.y;
                base[2*68 + srow] = ra0.z; base[3*68 + srow] = ra0.w;
                int j1 = srow + 32;
                if (j1 < ncols) {
                    base[0*68 + j1] = ra1.x; base[1*68 + j1] = ra1.y;
                    base[2*68 + j1] = ra1.z; base[3*68 + j1] = ra1.w;
                }
            }
        }
        __syncthreads();
        p ^= 1;
    }

    // partial-sum reduction across the 4 k-slices + fused epilogue
    #pragma unroll
    for (int r = 0; r < 6; r++) {
        float4 o;
        o.x = lo32(acc2[r][0]); o.y = hi32(acc2[r][0]);
        o.z = lo32(acc2[r][1]); o.w = hi32(acc2[r][1]);
        *reinterpret_cast<float4*>(s_red + slice*1536 + (r0 + r)*64 + c0) = o;
    }
    __syncthreads();
    #pragma unroll
    for (int u = 0; u < 6; u++) {
        int o = u*256 + tid;
        int row = o >> 6, col = o & 63;
        if (row < NSLOT && col < ncols) {
            float v = s_red[o] + s_red[1536+o] + s_red[3072+o] + s_red[4608+o];
            float rv;
            if (s_invp) {
                rv = v * s_invp[row];
            } else {
                rv = v * scale + (bias ? bias[col] : 0.f);
                if (relu) rv = fmaxf(rv, 0.f);
                if (s_res) rv += s_res[row*LDA + res_off + col];
            }
            if (g_out) g_out[(size_t)row * g_ld + col] = rv;
            if (s_out) s_out[row * s_ld + col] = rv;
        }
    }
    __syncthreads();
}

// per-row LN of smem 21x256 (warp per row), params from smem
__device__ __forceinline__ void ln_rows(const float* __restrict__ s_src,
                                        float* __restrict__ s_dst,
                                        const float* __restrict__ gg,
                                        const float* __restrict__ bb)
{
    int tid = threadIdx.x;
    int w = tid >> 5, lane = tid & 31;
    for (int row = w; row < NSLOT; row += 8) {
        const float* src = s_src + row*LDA;
        float v[8]; float s = 0.f;
        #pragma unroll
        for (int m = 0; m < 8; m++) { v[m] = src[lane + 32*m]; s += v[m]; }
        s = warpSum(s);
        float mean = s * (1.f/256.f);
        float s2 = 0.f;
        #pragma unroll
        for (int m = 0; m < 8; m++) { float d = v[m]-mean; s2 += d*d; }
        s2 = warpSum(s2);
        float inv = rsqrtf(s2 * (1.f/256.f) + LN_EPS);
        float* dst = s_dst + row*LDA;
        #pragma unroll
        for (int m = 0; m < 8; m++) {
            int d = lane + 32*m;
            dst[d] = (v[m]-mean) * inv * gg[d] + bb[d];
        }
    }
}

// load 21x256 global (ld 256) -> smem (ld LDA)
__device__ __forceinline__ void load_act(float* __restrict__ s_dst,
                                         const float* __restrict__ g_src)
{
    int tid = threadIdx.x;
    for (int i = tid; i < NSLOT*64; i += 256) {
        int row = i >> 6, c4 = i & 63;
        *reinterpret_cast<float4*>(&s_dst[row*LDA + c4*4]) =
            *reinterpret_cast<const float4*>(&g_src[(size_t)row*256 + c4*4]);
    }
}

__global__ void __cluster_dims__(4,1,1) __launch_bounds__(256,1)
slot_iter_kernel(const float* __restrict__ kb, const float* __restrict__ vb,
                 float* __restrict__ slots_g, float* __restrict__ q_g,
                 float* __restrict__ attn_g, float* __restrict__ upd_g,
                 float* __restrict__ h_g, float* __restrict__ f1_g,
                 const float* __restrict__ Wqt, const float* __restrict__ bq,
                 const float* __restrict__ W1t, const float* __restrict__ b1,
                 const float* __restrict__ W2t, const float* __restrict__ b2,
                 const float* __restrict__ Wiht, const float* __restrict__ b_ih,
                 const float* __restrict__ Whht, const float* __restrict__ b_hh,
                 const float* __restrict__ g_sl, const float* __restrict__ be_sl,
                 const float* __restrict__ g_ff, const float* __restrict__ be_ff,
                 float* __restrict__ out_attn)
{
    extern __shared__ float sm[];
    int tid = threadIdx.x;
    int b = blockIdx.x >> 2;
    int r = blockIdx.x & 3;

    float* s_slots = sm + OFF_SLOTS;
    float* s_sln   = sm + OFF_SLN;     // reused as s_gi after q-gemm
    float* s_q     = sm + OFF_Q;       // reused as s_gh after dots-gemm
    float* s_upd   = sm + OFF_UPD;
    float* s_h     = sm + OFF_H;
    float* s_hln   = sm + OFF_HLN;
    float* s_f1    = sm + OFF_F1;
    float* s_attn  = sm + OFF_ATTN;
    float* s_dots  = sm + OFF_DOTS;
    float* s_inv   = sm + OFF_INV;
    float* s_lnp   = sm + OFF_LNP;
    float* s_red   = sm + OFF_RED;
    float* s_buf   = sm + OFF_BUF;
    float* s_gi    = s_sln;            // [21][LDG3], cols t*64+c
    float* s_gh    = s_q;

    float* slots_b = slots_g + (size_t)b * NSLOT * 256;
    float* q_b     = q_g     + (size_t)b * NSLOT * 256;
    float* attn_b  = attn_g  + (size_t)b * NSLOT * HW;
    float* upd_b   = upd_g   + (size_t)b * NSLOT * 256;
    float* h_b     = h_g     + (size_t)b * NSLOT * 256;
    float* f1_b    = f1_g    + (size_t)b * NSLOT * 256;

    for (int i = tid; i < 256; i += 256) {
        s_lnp[i]       = g_sl[i];
        s_lnp[i + 256] = be_sl[i];
        s_lnp[i + 512] = g_ff[i];
        s_lnp[i + 768] = be_ff[i];
    }
    load_act(s_slots, slots_b);
    __syncthreads();

    for (int f = 0; f < NFRM; f++) {
        const float* kf = kb + (size_t)(b*NFRM + f) * HW * 256;   // [j][d]
        const float* vf = vb + (size_t)(b*NFRM + f) * HW * 256;   // [j][d]
        for (int it = 0; it < 3; it++) {
            // ---- A: LN(slots) -> q slice ----
            ln_rows(s_slots, s_sln, s_lnp, s_lnp + 256);
            __syncthreads();
            rb_gemm<0>(s_sln, LDA, 256, s_red, s_buf, Wqt + r*64, 256, bq + r*64,
                       64, 1.f, 0, nullptr, 0, nullptr, q_b + r*64, 256, nullptr, 0);
            cluster_sync_all();
            load_act(s_q, q_b);
            __syncthreads();

            // ---- B1: dots slice (48 j-cols, transpose-staged keys) + softmax ----
            rb_gemm<1>(s_q, LDA, 256, s_red, s_buf, kf + (size_t)(r*48)*256, 256, nullptr,
                       48, SCALE, 0, nullptr, 0, nullptr, nullptr, 0, s_dots, LDDOT);
            if (tid < 48) {
                int j = tid;
                float m = -1e30f;
                #pragma unroll
                for (int i = 0; i < NSLOT; i++) m = fmaxf(m, s_dots[i*LDDOT + j]);
                float e[NSLOT]; float sum = 0.f;
                #pragma unroll
                for (int i = 0; i < NSLOT; i++) { e[i] = expf(s_dots[i*LDDOT + j] - m); sum += e[i]; }
                float inv = 1.f / sum;
                int jg = r*48 + j;
                float* oa = out_attn + ((size_t)(b*NFRM + f) * NSLOT) * HW;
                #pragma unroll
                for (int i = 0; i < NSLOT; i++) {
                    float a = e[i]*inv + ATTN_EPS;
                    attn_b[(size_t)i*HW + jg] = a;
                    if (it == 2) oa[(size_t)i*HW + jg] = a;
                }
            }
            cluster_sync_all();

            // ---- B2: row-normalize + updates slice ----
            for (int i = tid; i < NSLOT*48; i += 256) {
                int row = i / 48, c4 = i % 48;
                *reinterpret_cast<float4*>(&s_attn[row*LDATTN + c4*4]) =
                    *reinterpret_cast<const float4*>(&attn_b[(size_t)row*HW + c4*4]);
            }
            __syncthreads();
            {
                int w = tid >> 5, lane = tid & 31;
                for (int row = w; row < NSLOT; row += 8) {
                    float s = 0.f;
                    for (int j = lane; j < HW; j += 32) s += s_attn[row*LDATTN + j];
                    s = warpSum(s);
                    if (lane == 0) s_inv[row] = 1.f / s;
                }
            }
            __syncthreads();
            rb_gemm<0>(s_attn, LDATTN, 192, s_red, s_buf, vf + r*64, 256, nullptr,
                       64, 1.f, 0, nullptr, 0, s_inv, upd_b + r*64, 256, nullptr, 0);
            cluster_sync_all();
            load_act(s_upd, upd_b);
            __syncthreads();

            // ---- C: GRU gemms, RANK-LOCAL columns cb = t*256 + r*64 ----
            // gi -> s_gi (overwrites dead s_sln), gh -> s_gh (dead s_q)
            #pragma unroll
            for (int t = 0; t < 3; t++) {
                int cb = t*256 + r*64;
                rb_gemm<0>(s_upd, LDA, 256, s_red, s_buf, Wiht + cb, 768, b_ih + cb,
                           64, 1.f, 0, nullptr, 0, nullptr, nullptr, 0, s_gi + t*64, LDG3);
                rb_gemm<0>(s_slots, LDA, 256, s_red, s_buf, Whht + cb, 768, b_hh + cb,
                           64, 1.f, 0, nullptr, 0, nullptr, nullptr, 0, s_gh + t*64, LDG3);
            }
            // ---- gate (rank-local, reads smem gi/gh) ----
            for (int idx = tid; idx < NSLOT*64; idx += 256) {
                int i = idx >> 6; int c = idx & 63; int d = r*64 + c;
                float ir = s_gi[i*LDG3 + c],      hr = s_gh[i*LDG3 + c];
                float iz = s_gi[i*LDG3 + 64 + c], hz = s_gh[i*LDG3 + 64 + c];
                float inn= s_gi[i*LDG3 + 128 + c],hn = s_gh[i*LDG3 + 128 + c];
                float hp = s_slots[i*LDA + d];
                float rr = 1.f / (1.f + expf(-(ir + hr)));
                float zz = 1.f / (1.f + expf(-(iz + hz)));
                float nn = tanhf(inn + rr * hn);
                h_b[(size_t)i*256 + d] = (1.f - zz) * nn + zz * hp;
            }
            cluster_sync_all();
            load_act(s_h, h_b);
            __syncthreads();
            ln_rows(s_h, s_hln, s_lnp + 512, s_lnp + 768);
            __syncthreads();

            // ---- D: MLP ----
            rb_gemm<0>(s_hln, LDA, 256, s_red, s_buf, W1t + r*64, 256, b1 + r*64,
                       64, 1.f, 1, nullptr, 0, nullptr, f1_b + r*64, 256, nullptr, 0);
            cluster_sync_all();
            load_act(s_f1, f1_b);
            __syncthreads();
            rb_gemm<0>(s_f1, LDA, 256, s_red, s_buf, W2t + r*64, 256, b2 + r*64,
                       64, 1.f, 0, s_h, r*64, nullptr, slots_b + r*64, 256, nullptr, 0);
            cluster_sync_all();
            load_act(s_slots, slots_b);
            __syncthreads();
        }
    }
}

// ---------------- final slots copy (first 20 of 21 slots) ----------------
__global__ void copy_slots_kernel(const float* __restrict__ slots, float* __restrict__ out) {
    int idx = blockIdx.x * 256 + threadIdx.x;
    int d = idx & 255;
    int s = (idx >> 8) % NACT;
    int b = idx / (NACT * DIM);
    out[idx] = slots[((size_t)(b * NSLOT + s) << 8) + d];
}

// ---------------- launch ----------------
extern "C" void kernel_launch(void* const* d_in, const int* in_sizes, int n_in,
                              void* d_out, int out_size) {
    const float* inputs = (const float*)d_in[0];
    const float* noise  = (const float*)d_in[1];
    const float* mu     = (const float*)d_in[2];
    const float* sigma  = (const float*)d_in[3];
    const float* Wq = (const float*)d_in[4];  const float* bq = (const float*)d_in[5];
    const float* Wk = (const float*)d_in[6];  const float* bk = (const float*)d_in[7];
    const float* Wv = (const float*)d_in[8];  const float* bv = (const float*)d_in[9];
    const float* W1 = (const float*)d_in[10]; const float* b1 = (const float*)d_in[11];
    const float* W2 = (const float*)d_in[12]; const float* b2 = (const float*)d_in[13];
    const float* W_ih = (const float*)d_in[14]; const float* b_ih = (const float*)d_in[15];
    const float* W_hh = (const float*)d_in[16]; const float* b_hh = (const float*)d_in[17];
    const float* g_in_p = (const float*)d_in[18]; const float* be_in = (const float*)d_in[19];
    const float* g_sl_p = (const float*)d_in[20]; const float* be_sl = (const float*)d_in[21];
    const float* g_ff_p = (const float*)d_in[22]; const float* be_ff = (const float*)d_in[23];
    float* out = (float*)d_out;

    float *xn, *kb, *vb, *slots, *qb, *attnO, *upd, *hb, *f1;
    float *wqt, *w1t, *w2t, *wiht, *whht;
    cudaGetSymbolAddress((void**)&xn,    g_xn);
    cudaGetSymbolAddress((void**)&kb,    g_k);
    cudaGetSymbolAddress((void**)&vb,    g_v);
    cudaGetSymbolAddress((void**)&slots, g_slots);
    cudaGetSymbolAddress((void**)&qb,    g_q);
    cudaGetSymbolAddress((void**)&attnO, g_attn);
    cudaGetSymbolAddress((void**)&upd,   g_upd);
    cudaGetSymbolAddress((void**)&hb,    g_h);
    cudaGetSymbolAddress((void**)&f1,    g_f1);
    cudaGetSymbolAddress((void**)&wqt,   g_wqt);
    cudaGetSymbolAddress((void**)&w1t,   g_w1t);
    cudaGetSymbolAddress((void**)&w2t,   g_w2t);
    cudaGetSymbolAddress((void**)&wiht,  g_wiht);
    cudaGetSymbolAddress((void**)&whht,  g_whht);

    cudaFuncSetAttribute(slot_iter_kernel,
                         cudaFuncAttributeMaxDynamicSharedMemorySize, SMEM_BYTES);

    // 1: slots0 + all weight transposes
    prep_kernel<<<672 + 64*3 + 192*2, 256>>>(noise, mu, sigma, slots,
                                             Wq, wqt, W1, w1t, W2, w2t,
                                             W_ih, wiht, W_hh, whht);
    // 2: LN(inputs)
    ln_kernel<<<ROWS_KV, 256>>>(inputs, g_in_p, be_in, xn);
    // 3: fused K/V projections
    dim3 gkv(DIM / BN, ROWS_KV / BM, 2);
    gemmkv_kernel<<<gkv, 256>>>(xn, Wk, bk, kb, Wv, bv, vb);
    // 4: persistent iteration kernel (profiled launch)
    float* attn_out = out + SLOTS_OUT_SIZE;
    slot_iter_kernel<<<BATCH * 4, 256, SMEM_BYTES>>>(
        kb, vb, slots, qb, attnO, upd, hb, f1,
        wqt, bq, w1t, b1, w2t, b2, wiht, b_ih, whht, b_hh,
        g_sl_p, be_sl, g_ff_p, be_ff, attn_out);
    // 5: output copy
    copy_slots_kernel<<<SLOTS_OUT_SIZE / 256, 256>>>(slots, out);
}